// round 14
// baseline (speedup 1.0000x reference)
#include <cuda_runtime.h>
#include <math.h>
#include <stdint.h>

#define BATCH   4
#define CH      64
#define NTOK    4096
#define TOKALL  16384
#define QSCALE  (0.125f * 1.4426950408889634f)   // scale * log2(e)
#define BUF_FLOATS 1048576

__device__ float g_scratch[14 * BUF_FLOATS];
__device__ float g_gap[BATCH * CH];

__device__ __forceinline__ float gelu_exact(float x) {
    return 0.5f * x * (1.0f + erff(x * 0.70710678118654752440f));
}
__device__ __forceinline__ float tf32r(float x) {
    float r; asm("cvt.rna.tf32.f32 %0, %1;" : "=f"(r) : "f"(x)); return r;
}
__device__ __forceinline__ float ex2(float x) {
    float r; asm("ex2.approx.f32 %0, %1;" : "=f"(r) : "f"(x)); return r;
}
__device__ __forceinline__ void mma_tf32(float d[4], const unsigned a[4], unsigned b0, unsigned b1) {
    asm("mma.sync.aligned.m16n8k8.row.col.f32.tf32.tf32.f32 "
        "{%0,%1,%2,%3},{%4,%5,%6,%7},{%8,%9},{%0,%1,%2,%3};"
        : "+f"(d[0]), "+f"(d[1]), "+f"(d[2]), "+f"(d[3])
        : "r"(a[0]), "r"(a[1]), "r"(a[2]), "r"(a[3]), "r"(b0), "r"(b1));
}
__device__ __forceinline__ void barg(int id) {
    asm volatile("bar.sync %0, 256;" :: "r"(id) : "memory");
}

// W pair-packing position for element (o, ci): {W[o][8ks+mm], W[o][8ks+mm+4]}
__device__ __forceinline__ int wpos(int o, int ci) {
    return (ci >> 3) * 512 + o * 8 + (ci & 3) * 2 + ((ci >> 2) & 1);
}
// A-fragments for rows r0, r0+8 from X[.][68] tile (tf32 pre-converted).
__device__ __forceinline__ void load_afrag(unsigned a[8][4], const float* X, int r0, int mm) {
#pragma unroll
    for (int ks = 0; ks < 8; ks++) {
        a[ks][0] = __float_as_uint(X[r0 * 68 + 8 * ks + mm]);
        a[ks][1] = __float_as_uint(X[(r0 + 8) * 68 + 8 * ks + mm]);
        a[ks][2] = __float_as_uint(X[r0 * 68 + 8 * ks + mm + 4]);
        a[ks][3] = __float_as_uint(X[(r0 + 8) * 68 + 8 * ks + mm + 4]);
    }
}
// 8-nt variants (full 64-col row per warp)
__device__ __forceinline__ void init_acc(float acc[8][4], const float* bs, int mm) {
#pragma unroll
    for (int nt = 0; nt < 8; nt++) {
        float b0 = bs[8 * nt + 2 * mm], b1 = bs[8 * nt + 2 * mm + 1];
        acc[nt][0] = b0; acc[nt][1] = b1; acc[nt][2] = b0; acc[nt][3] = b1;
    }
}
__device__ __forceinline__ void mm_core(float acc[8][4], const unsigned a[8][4],
                                        const float* WsP, int gr, int mm) {
#pragma unroll
    for (int ks = 0; ks < 8; ks++)
#pragma unroll
        for (int nt = 0; nt < 8; nt++) {
            float2 bb = *reinterpret_cast<const float2*>(&WsP[ks * 512 + (8 * nt + gr) * 8 + mm * 2]);
            mma_tf32(acc[nt], a[ks], __float_as_uint(bb.x), __float_as_uint(bb.y));
        }
}
__device__ __forceinline__ void store_acc(const float acc[8][4], float* out,
                                          int t0, int r0, int mm) {
#pragma unroll
    for (int nt = 0; nt < 8; nt++) {
        *reinterpret_cast<float2*>(&out[(size_t)(t0 + r0) * 64 + 8 * nt + 2 * mm]) =
            make_float2(acc[nt][0], acc[nt][1]);
        *reinterpret_cast<float2*>(&out[(size_t)(t0 + r0 + 8) * 64 + 8 * nt + 2 * mm]) =
            make_float2(acc[nt][2], acc[nt][3]);
    }
}
// 4-nt variants (N-split: warp owns cols [8*nt0, 8*nt0+32))
__device__ __forceinline__ void init_acc4(float acc[4][4], const float* bs, int mm, int nt0) {
#pragma unroll
    for (int nt = 0; nt < 4; nt++) {
        float b0 = bs[8 * (nt0 + nt) + 2 * mm], b1 = bs[8 * (nt0 + nt) + 2 * mm + 1];
        acc[nt][0] = b0; acc[nt][1] = b1; acc[nt][2] = b0; acc[nt][3] = b1;
    }
}
__device__ __forceinline__ void mm_core4(float acc[4][4], const unsigned a[8][4],
                                         const float* WsP, int gr, int mm, int nt0) {
#pragma unroll
    for (int ks = 0; ks < 8; ks++)
#pragma unroll
        for (int nt = 0; nt < 4; nt++) {
            float2 bb = *reinterpret_cast<const float2*>(
                &WsP[ks * 512 + (8 * (nt0 + nt) + gr) * 8 + mm * 2]);
            mma_tf32(acc[nt], a[ks], __float_as_uint(bb.x), __float_as_uint(bb.y));
        }
}
__device__ __forceinline__ void store_acc4(const float acc[4][4], float* out,
                                           int t0, int r0, int mm, int nt0) {
#pragma unroll
    for (int nt = 0; nt < 4; nt++) {
        int c0 = 8 * (nt0 + nt) + 2 * mm;
        *reinterpret_cast<float2*>(&out[(size_t)(t0 + r0) * 64 + c0]) =
            make_float2(acc[nt][0], acc[nt][1]);
        *reinterpret_cast<float2*>(&out[(size_t)(t0 + r0 + 8) * 64 + c0]) =
            make_float2(acc[nt][2], acc[nt][3]);
    }
}

// ---------------------------------------------------------------------------
// avgpool 2x2: x [B,C,128,128] -> xp tokens [B*N, C]
// ---------------------------------------------------------------------------
__global__ void avgpool_kernel(const float* __restrict__ x, float* __restrict__ xp) {
    int b  = blockIdx.x >> 6;
    int hp = blockIdx.x & 63;
    const float* xb = x + (size_t)b * CH * 128 * 128;
    float* xpb = xp + ((size_t)b * NTOK + (size_t)hp * 64) * CH;
    for (int idx = threadIdx.x; idx < 64 * CH; idx += blockDim.x) {
        int c  = idx & 63;
        int wp = idx >> 6;
        const float* p = xb + ((size_t)c * 128 + 2 * hp) * 128 + 2 * wp;
        xpb[(size_t)wp * CH + c] = 0.25f * (p[0] + p[1] + p[128] + p[129]);
    }
}

__global__ void gap_kernel(const float* __restrict__ x, float* __restrict__ gap) {
    int bc = blockIdx.x;
    const float* p = x + (size_t)bc * 16384;
    float s = 0.f;
    for (int i = threadIdx.x; i < 16384; i += 256) s += p[i];
    __shared__ float red[256];
    red[threadIdx.x] = s;
    __syncthreads();
    for (int st = 128; st > 0; st >>= 1) {
        if (threadIdx.x < st) red[threadIdx.x] += red[threadIdx.x + st];
        __syncthreads();
    }
    if (threadIdx.x == 0) gap[bc] = red[0] * (1.0f / 16384.0f);
}

// ---------------------------------------------------------------------------
// Composed strip weights
// ---------------------------------------------------------------------------
__global__ void comb_kernel(const float* __restrict__ convh_w, const float* __restrict__ convh_b,
                            const float* __restrict__ sch_pw, const float* __restrict__ sch_pwb,
                            const float* __restrict__ scv_pw, const float* __restrict__ scv_pwb,
                            float* __restrict__ comb_h, float* __restrict__ comb_v,
                            float* __restrict__ bias_comb) {
    extern __shared__ float s[];
    float* A = s; float* B1 = s + 4096; float* B2 = s + 8192;
    int tid = threadIdx.x;
    for (int idx = tid; idx < 4096; idx += 256) {
        A[idx] = convh_w[idx]; B1[idx] = sch_pw[idx]; B2[idx] = scv_pw[idx];
    }
    __syncthreads();
    for (int e = tid; e < 4096; e += 256) {
        int o = e >> 6, j = e & 63;
        float sh = 0.f, sv = 0.f;
        for (int i = 0; i < 64; i++) {
            float a = A[o * 64 + i];
            sh += a * B1[i * 64 + j];
            sv += a * B2[i * 64 + j];
        }
        comb_h[o * 64 + j] = sh;
        comb_v[o * 64 + j] = sv;
    }
    if (tid < 64) {
        float sb = 0.f;
        for (int i = 0; i < 64; i++) sb += A[tid * 64 + i] * (sch_pwb[i] + scv_pwb[i]);
        bias_comb[tid] = convh_b[tid] + sb;
    }
}

// ---------------------------------------------------------------------------
// TC qkvo, 512 threads: warps 0-7 -> q,k ; warps 8-15 -> v,xV.
// grid 128. smem 34048 floats.
// ---------------------------------------------------------------------------
__global__ void qkvo_tc_kernel(const float* __restrict__ xp, const float* __restrict__ gap,
                               const float* __restrict__ Wq, const float* __restrict__ bq,
                               const float* __restrict__ Wk, const float* __restrict__ bk,
                               const float* __restrict__ Wv, const float* __restrict__ bv,
                               const float* __restrict__ Wo, const float* __restrict__ bo,
                               float* __restrict__ q, float* __restrict__ k,
                               float* __restrict__ v, float* __restrict__ xV) {
    extern __shared__ __align__(16) float sm[];
    float* Xg  = sm;            // 8704
    float* Xs  = sm + 8704;     // 8704
    float* Wp4 = sm + 17408;    // 16384
    float* bs  = sm + 33792;    // 256
    int tid = threadIdx.x;
    int t0 = blockIdx.x * 128;
    int b = t0 >> 12;
    for (int idx = tid; idx < 8192; idx += 512) {
        int t = idx >> 6, c = idx & 63;
        float xv = xp[(size_t)(t0 + t) * 64 + c];
        Xs[t * 68 + c] = tf32r(xv);
        Xg[t * 68 + c] = tf32r(xv * __ldg(&gap[b * 64 + c]));
    }
    for (int idx = tid; idx < 4096; idx += 512) {
        int o = idx >> 6, ci = idx & 63;
        int pos = wpos(o, ci);
        Wp4[pos]         = tf32r(Wq[idx]);
        Wp4[4096 + pos]  = tf32r(Wk[idx]);
        Wp4[8192 + pos]  = tf32r(Wv[idx]);
        Wp4[12288 + pos] = tf32r(Wo[idx]);
    }
    if (tid < 64) {
        bs[tid] = bq[tid]; bs[64 + tid] = bk[tid];
        bs[128 + tid] = bv[tid]; bs[192 + tid] = bo[tid];
    }
    __syncthreads();
    int warp = tid >> 5, lane = tid & 31, gr = lane >> 2, mm = lane & 3;
    int r0 = (warp & 7) * 16 + gr;
    unsigned a[8][4];
    float acc[8][4];
    if (warp < 8) {
        load_afrag(a, Xg, r0, mm);
        init_acc(acc, bs, mm);       mm_core(acc, a, Wp4, gr, mm);        store_acc(acc, q, t0, r0, mm);
        init_acc(acc, bs + 64, mm);  mm_core(acc, a, Wp4 + 4096, gr, mm); store_acc(acc, k, t0, r0, mm);
    } else {
        load_afrag(a, Xg, r0, mm);
        init_acc(acc, bs + 128, mm); mm_core(acc, a, Wp4 + 8192, gr, mm); store_acc(acc, v, t0, r0, mm);
        load_afrag(a, Xs, r0, mm);
        init_acc(acc, bs + 192, mm); mm_core(acc, a, Wp4 + 12288, gr, mm); store_acc(acc, xV, t0, r0, mm);
    }
}

// ---------------------------------------------------------------------------
// TC 64x64 linear, 512 threads N-split (no LN). grid 128. smem 12864 fl.
// ---------------------------------------------------------------------------
__global__ void linear_tc2_kernel(const float* __restrict__ in0, const float* __restrict__ W,
                                  const float* __restrict__ bias, const float* __restrict__ res,
                                  float* __restrict__ out) {
    extern __shared__ __align__(16) float sm[];
    float* Xs  = sm;           // 8704
    float* WsP = sm + 8704;    // 4096
    float* bs  = sm + 12800;   // 64
    int tid = threadIdx.x;
    int t0 = blockIdx.x * 128;
    for (int idx = tid; idx < 8192; idx += 512) {
        int t = idx >> 6, c = idx & 63;
        Xs[t * 68 + c] = tf32r(in0[(size_t)(t0 + t) * 64 + c]);
    }
    for (int idx = tid; idx < 4096; idx += 512) {
        int o = idx >> 6, ci = idx & 63;
        WsP[wpos(o, ci)] = tf32r(W[idx]);
    }
    if (tid < 64) bs[tid] = bias[tid];
    __syncthreads();
    int warp = tid >> 5, lane = tid & 31, gr = lane >> 2, mm = lane & 3;
    int r0 = (warp & 7) * 16 + gr;
    int nt0 = (warp >> 3) * 4;
    unsigned a[8][4];
    load_afrag(a, Xs, r0, mm);
    float acc[4][4];
    init_acc4(acc, bs, mm, nt0);
    mm_core4(acc, a, WsP, gr, mm, nt0);
    if (res) {
#pragma unroll
        for (int nt = 0; nt < 4; nt++) {
            int c0 = 8 * (nt0 + nt) + 2 * mm;
            float2 r0v = *reinterpret_cast<const float2*>(&res[(size_t)(t0 + r0) * 64 + c0]);
            float2 r1v = *reinterpret_cast<const float2*>(&res[(size_t)(t0 + r0 + 8) * 64 + c0]);
            acc[nt][0] += r0v.x; acc[nt][1] += r0v.y;
            acc[nt][2] += r1v.x; acc[nt][3] += r1v.y;
        }
    }
    store_acc4(acc, out, t0, r0, mm, nt0);
}

// ---------------------------------------------------------------------------
// TC linear + residual + LayerNorm (Wp path). 256 threads, grid 128.
// ---------------------------------------------------------------------------
__global__ void linear_ln_kernel(const float* __restrict__ in0, const float* __restrict__ W,
                                 const float* __restrict__ bias, const float* __restrict__ res,
                                 const float* __restrict__ lng, const float* __restrict__ lnb,
                                 float* __restrict__ out) {
    extern __shared__ __align__(16) float sm[];
    float* Xs  = sm;           // 8704
    float* WsP = sm + 8704;    // 4096
    float* bs  = sm + 12800;   // 64
    float* lg  = sm + 12864;   // 64
    float* lb  = sm + 12928;   // 64
    int tid = threadIdx.x;
    int t0 = blockIdx.x * 128;
    for (int idx = tid; idx < 8192; idx += 256) {
        int t = idx >> 6, c = idx & 63;
        Xs[t * 68 + c] = tf32r(in0[(size_t)(t0 + t) * 64 + c]);
    }
    for (int idx = tid; idx < 4096; idx += 256) {
        int o = idx >> 6, ci = idx & 63;
        WsP[wpos(o, ci)] = tf32r(W[idx]);
    }
    if (tid < 64) { bs[tid] = bias[tid]; lg[tid] = lng[tid]; lb[tid] = lnb[tid]; }
    __syncthreads();
    int warp = tid >> 5, lane = tid & 31, gr = lane >> 2, mm = lane & 3;
    int r0 = warp * 16 + gr;
    unsigned a[8][4];
    load_afrag(a, Xs, r0, mm);
    float acc[8][4];
    init_acc(acc, bs, mm);
    mm_core(acc, a, WsP, gr, mm);
#pragma unroll
    for (int nt = 0; nt < 8; nt++) {
        float2 r0v = *reinterpret_cast<const float2*>(&res[(size_t)(t0 + r0) * 64 + 8 * nt + 2 * mm]);
        float2 r1v = *reinterpret_cast<const float2*>(&res[(size_t)(t0 + r0 + 8) * 64 + 8 * nt + 2 * mm]);
        acc[nt][0] += r0v.x; acc[nt][1] += r0v.y;
        acc[nt][2] += r1v.x; acc[nt][3] += r1v.y;
    }
    float s0 = 0.f, s1 = 0.f;
#pragma unroll
    for (int nt = 0; nt < 8; nt++) { s0 += acc[nt][0] + acc[nt][1]; s1 += acc[nt][2] + acc[nt][3]; }
    s0 += __shfl_xor_sync(0xffffffffu, s0, 1); s0 += __shfl_xor_sync(0xffffffffu, s0, 2);
    s1 += __shfl_xor_sync(0xffffffffu, s1, 1); s1 += __shfl_xor_sync(0xffffffffu, s1, 2);
    float mu0 = s0 * (1.0f / 64.0f), mu1 = s1 * (1.0f / 64.0f);
    float q0 = 0.f, q1 = 0.f;
#pragma unroll
    for (int nt = 0; nt < 8; nt++) {
        float d0 = acc[nt][0] - mu0, d1 = acc[nt][1] - mu0;
        float d2 = acc[nt][2] - mu1, d3 = acc[nt][3] - mu1;
        q0 += d0 * d0 + d1 * d1; q1 += d2 * d2 + d3 * d3;
    }
    q0 += __shfl_xor_sync(0xffffffffu, q0, 1); q0 += __shfl_xor_sync(0xffffffffu, q0, 2);
    q1 += __shfl_xor_sync(0xffffffffu, q1, 1); q1 += __shfl_xor_sync(0xffffffffu, q1, 2);
    float rstd0 = rsqrtf(q0 * (1.0f / 64.0f) + 1e-5f);
    float rstd1 = rsqrtf(q1 * (1.0f / 64.0f) + 1e-5f);
#pragma unroll
    for (int nt = 0; nt < 8; nt++) {
        int c0 = 8 * nt + 2 * mm;
        acc[nt][0] = (acc[nt][0] - mu0) * rstd0 * lg[c0] + lb[c0];
        acc[nt][1] = (acc[nt][1] - mu0) * rstd0 * lg[c0 + 1] + lb[c0 + 1];
        acc[nt][2] = (acc[nt][2] - mu1) * rstd1 * lg[c0] + lb[c0];
        acc[nt][3] = (acc[nt][3] - mu1) * rstd1 * lg[c0 + 1] + lb[c0 + 1];
    }
    store_acc(acc, out, t0, r0, mm);
}

// ---------------------------------------------------------------------------
// TC strip branch, 512 threads N-split. grid 128. smem 25664 fl.
// ---------------------------------------------------------------------------
__global__ void strip_tc_kernel(const float* __restrict__ xp,
                                const float* __restrict__ sch_dw, const float* __restrict__ sch_dwb,
                                const float* __restrict__ scv_dw, const float* __restrict__ scv_dwb,
                                const float* __restrict__ comb_h, const float* __restrict__ comb_v,
                                const float* __restrict__ bias_comb, float* __restrict__ out) {
    extern __shared__ __align__(16) float sm[];
    float* Gh   = sm;           // 8704
    float* Gv   = sm + 8704;    // 8704
    float* WsPH = sm + 17408;   // 4096
    float* WsPV = sm + 21504;   // 4096
    float* bs   = sm + 25600;   // 64
    int tid = threadIdx.x;
    int t0 = blockIdx.x * 128;
    for (int idx = tid; idx < 8192; idx += 512) {
        int tt = idx >> 6, ci = idx & 63;
        int token = t0 + tt;
        int h = (token >> 6) & 63, w = token & 63;
        size_t base = (size_t)token * 64 + ci;
        float ah = sch_dwb[ci], av = scv_dwb[ci];
#pragma unroll
        for (int d = -2; d <= 2; d++) {
            int hh = h + d;
            if (hh >= 0 && hh < 64) ah += sch_dw[ci * 5 + d + 2] * xp[base + (ptrdiff_t)d * 4096];
            int ww = w + d;
            if (ww >= 0 && ww < 64) av += scv_dw[ci * 5 + d + 2] * xp[base + (ptrdiff_t)d * 64];
        }
        Gh[tt * 68 + ci] = tf32r(gelu_exact(ah));
        Gv[tt * 68 + ci] = tf32r(gelu_exact(av));
    }
    for (int idx = tid; idx < 4096; idx += 512) {
        int o = idx >> 6, ci = idx & 63;
        int pos = wpos(o, ci);
        WsPH[pos] = tf32r(comb_h[idx]);
        WsPV[pos] = tf32r(comb_v[idx]);
    }
    if (tid < 64) bs[tid] = bias_comb[tid];
    __syncthreads();
    int warp = tid >> 5, lane = tid & 31, gr = lane >> 2, mm = lane & 3;
    int r0 = (warp & 7) * 16 + gr;
    int nt0 = (warp >> 3) * 4;
    unsigned a[8][4];
    float acc[4][4];
    init_acc4(acc, bs, mm, nt0);
    load_afrag(a, Gh, r0, mm); mm_core4(acc, a, WsPH, gr, mm, nt0);
    load_afrag(a, Gv, r0, mm); mm_core4(acc, a, WsPV, gr, mm, nt0);
    store_acc4(acc, out, t0, r0, mm, nt0);
}

// ---------------------------------------------------------------------------
// TC dsc, 512 threads N-split: gelu(dw3x3(pn)) staged, matmul, +pn residual.
// ---------------------------------------------------------------------------
__global__ void dsc_tc_kernel(const float* __restrict__ pn,
                              const float* __restrict__ dsc_dw, const float* __restrict__ dsc_dwb,
                              const float* __restrict__ dsc_pw, const float* __restrict__ dsc_pwb,
                              float* __restrict__ out) {
    extern __shared__ __align__(16) float sm[];
    float* Xs  = sm;           // 8704
    float* WsP = sm + 8704;    // 4096
    float* bs  = sm + 12800;   // 64
    int tid = threadIdx.x;
    int t0 = blockIdx.x * 128;
    for (int idx = tid; idx < 8192; idx += 512) {
        int tt = idx >> 6, ci = idx & 63;
        int token = t0 + tt;
        int b = token >> 12;
        int h = (token >> 6) & 63, w = token & 63;
        float acc = dsc_dwb[ci];
#pragma unroll
        for (int ky = 0; ky < 3; ky++) {
#pragma unroll
            for (int kx = 0; kx < 3; kx++) {
                int hh = h + ky - 1, ww = w + kx - 1;
                if (hh >= 0 && hh < 64 && ww >= 0 && ww < 64) {
                    size_t src = (((size_t)b << 12) | ((size_t)hh << 6) | (size_t)ww) * 64 + ci;
                    acc += dsc_dw[ci * 9 + ky * 3 + kx] * pn[src];
                }
            }
        }
        Xs[tt * 68 + ci] = tf32r(gelu_exact(acc));
    }
    for (int idx = tid; idx < 4096; idx += 512) {
        int o = idx >> 6, ci = idx & 63;
        WsP[wpos(o, ci)] = tf32r(dsc_pw[idx]);
    }
    if (tid < 64) bs[tid] = dsc_pwb[tid];
    __syncthreads();
    int warp = tid >> 5, lane = tid & 31, gr = lane >> 2, mm = lane & 3;
    int r0 = (warp & 7) * 16 + gr;
    int nt0 = (warp >> 3) * 4;
    unsigned a[8][4];
    load_afrag(a, Xs, r0, mm);
    float acc[4][4];
    init_acc4(acc, bs, mm, nt0);
    mm_core4(acc, a, WsP, gr, mm, nt0);
#pragma unroll
    for (int nt = 0; nt < 4; nt++) {
        int c0 = 8 * (nt0 + nt) + 2 * mm;
        float2 r0v = *reinterpret_cast<const float2*>(&pn[(size_t)(t0 + r0) * 64 + c0]);
        float2 r1v = *reinterpret_cast<const float2*>(&pn[(size_t)(t0 + r0 + 8) * 64 + c0]);
        acc[nt][0] += r0v.x; acc[nt][1] += r0v.y;
        acc[nt][2] += r1v.x; acc[nt][3] += r1v.y;
    }
    store_acc4(acc, out, t0, r0, mm, nt0);
}

// ---------------------------------------------------------------------------
// Tensor-core flash attention, 512 threads / 16 warps, TWO KEY-GROUPS.
// No-max softmax => attention is linear in exp(S): groups sum independently.
// Group g (warps 8g..8g+7) processes keys [g*2048, g*2048+2048) with its own
// K/V smem tiles and named barrier (1+g). Final combine via smem.
// grid (32, B). smem = 8704(Q) + 8192(K) + 8192(V) + 17408(Ps) fl = 169984 B.
// ---------------------------------------------------------------------------
__global__ void attn_tc_kernel(const float* __restrict__ Q, const float* __restrict__ K,
                               const float* __restrict__ V, float* __restrict__ O) {
    extern __shared__ __align__(16) float sm[];
    float* Qs  = sm;               // 8704
    float* KsP = sm + 8704;        // 2 * 4096
    float* VsP = sm + 8704 + 8192; // 2 * 4096
    float* Ps  = sm + 8704 + 16384;// 16 * 1088

    int b  = blockIdx.y;
    int qt = blockIdx.x;
    const float* Qb = Q + ((size_t)b * NTOK + (size_t)qt * 128) * 64;
    const float* Kb = K + (size_t)b * NTOK * 64;
    const float* Vb = V + (size_t)b * NTOK * 64;
    float* Ob = O + ((size_t)b * NTOK + (size_t)qt * 128) * 64;

    int tid  = threadIdx.x;
    int warp = tid >> 5, lane = tid & 31;
    int gr = lane >> 2, mm = lane & 3;
    int g = warp >> 3;              // key-group
    int tid256 = tid & 255;
    float* Kg  = KsP + g * 4096;
    float* Vg  = VsP + g * 4096;
    float* Psw = Ps + warp * 1088;

    for (int idx = tid; idx < 8192; idx += 512) {
        int i = idx >> 6, c = idx & 63;
        Qs[i * 68 + c] = tf32r(Qb[idx] * QSCALE);
    }
    __syncthreads();

    unsigned qa[8][4];
    int qrow = (warp & 7) * 16 + gr;
    load_afrag(qa, Qs, qrow, mm);

    float l0 = 0.f, l1 = 0.f;
    float o[8][4];
#pragma unroll
    for (int nt = 0; nt < 8; nt++)
#pragma unroll
        for (int e = 0; e < 4; e++) o[nt][e] = 0.f;

    for (int kk = 0; kk < 32; kk++) {
        int kt = g * 32 + kk;
        const float* Kt = Kb + (size_t)kt * 4096;
        const float* Vt = Vb + (size_t)kt * 4096;
        barg(1 + g);   // group: previous iteration's readers done
        // stage K/V pair-packed, vectorized LDG.128
        for (int i4 = tid256; i4 < 1024; i4 += 256) {
            int j = i4 >> 4, c4 = (i4 & 15) * 4;
            float4 kv = *reinterpret_cast<const float4*>(Kt + j * 64 + c4);
            Kg[wpos(j, c4 + 0)] = tf32r(kv.x);
            Kg[wpos(j, c4 + 1)] = tf32r(kv.y);
            Kg[wpos(j, c4 + 2)] = tf32r(kv.z);
            Kg[wpos(j, c4 + 3)] = tf32r(kv.w);
            float4 vv = *reinterpret_cast<const float4*>(Vt + j * 64 + c4);
            Vg[wpos(c4 + 0, j)] = tf32r(vv.x);
            Vg[wpos(c4 + 1, j)] = tf32r(vv.y);
            Vg[wpos(c4 + 2, j)] = tf32r(vv.z);
            Vg[wpos(c4 + 3, j)] = tf32r(vv.w);
        }
        barg(1 + g);

        // S' = Q K^T (log2 domain)
        float s[8][4];
#pragma unroll
        for (int nt = 0; nt < 8; nt++)
#pragma unroll
            for (int e = 0; e < 4; e++) s[nt][e] = 0.f;
#pragma unroll
        for (int ks = 0; ks < 8; ks++) {
#pragma unroll
            for (int nt = 0; nt < 8; nt++) {
                float2 bb = *reinterpret_cast<const float2*>(
                    &Kg[ks * 512 + (8 * nt + gr) * 8 + mm * 2]);
                mma_tf32(s[nt], qa[ks], __float_as_uint(bb.x), __float_as_uint(bb.y));
            }
        }

        // exp, accumulate l, store P to per-warp pad
        float rs0 = 0.f, rs1 = 0.f;
#pragma unroll
        for (int nt = 0; nt < 8; nt++) {
            float e0 = ex2(s[nt][0]), e1 = ex2(s[nt][1]);
            float e2 = ex2(s[nt][2]), e3 = ex2(s[nt][3]);
            rs0 += e0 + e1; rs1 += e2 + e3;
            *reinterpret_cast<float2*>(&Psw[gr * 68 + 8 * nt + 2 * mm]) =
                make_float2(tf32r(e0), tf32r(e1));
            *reinterpret_cast<float2*>(&Psw[(gr + 8) * 68 + 8 * nt + 2 * mm]) =
                make_float2(tf32r(e2), tf32r(e3));
        }
        l0 += rs0; l1 += rs1;
        __syncwarp();

        // O += P V
#pragma unroll
        for (int js = 0; js < 8; js++) {
            unsigned pa[4];
            pa[0] = __float_as_uint(Psw[gr * 68 + 8 * js + mm]);
            pa[1] = __float_as_uint(Psw[(gr + 8) * 68 + 8 * js + mm]);
            pa[2] = __float_as_uint(Psw[gr * 68 + 8 * js + mm + 4]);
            pa[3] = __float_as_uint(Psw[(gr + 8) * 68 + 8 * js + mm + 4]);
#pragma unroll
            for (int nt = 0; nt < 8; nt++) {
                float2 bb = *reinterpret_cast<const float2*>(
                    &Vg[js * 512 + (8 * nt + gr) * 8 + mm * 2]);
                mma_tf32(o[nt], pa, __float_as_uint(bb.x), __float_as_uint(bb.y));
            }
        }
        __syncwarp();
    }

    // quad-reduce l (rows qrow / qrow+8)
    l0 += __shfl_xor_sync(0xffffffffu, l0, 1); l0 += __shfl_xor_sync(0xffffffffu, l0, 2);
    l1 += __shfl_xor_sync(0xffffffffu, l1, 1); l1 += __shfl_xor_sync(0xffffffffu, l1, 2);

    // combine across the two key-groups: g1 -> smem, g0 adds & writes out
    float* Ocmb = KsP;      // 8192 fl = [128][64]
    float* lcmb = VsP;      // 128 fl
    __syncthreads();
    if (g == 1) {
#pragma unroll
        for (int nt = 0; nt < 8; nt++) {
            *reinterpret_cast<float2*>(&Ocmb[qrow * 64 + 8 * nt + 2 * mm]) =
                make_float2(o[nt][0], o[nt][1]);
            *reinterpret_cast<float2*>(&Ocmb[(qrow + 8) * 64 + 8 * nt + 2 * mm]) =
                make_float2(o[nt][2], o[nt][3]);
        }
        if (mm == 0) { lcmb[qrow] = l0; lcmb[qrow + 8] = l1; }
    }
    __syncthreads();
    if (g == 0) {
        l0 += lcmb[qrow]; l1 += lcmb[qrow + 8];
        float inv0 = 1.0f / l0, inv1 = 1.0f / l1;
#pragma unroll
        for (int nt = 0; nt < 8; nt++) {
            float2 a0 = *reinterpret_cast<const float2*>(&Ocmb[qrow * 64 + 8 * nt + 2 * mm]);
            float2 a1 = *reinterpret_cast<const float2*>(&Ocmb[(qrow + 8) * 64 + 8 * nt + 2 * mm]);
            *reinterpret_cast<float2*>(&Ob[(size_t)qrow * 64 + 8 * nt + 2 * mm]) =
                make_float2((o[nt][0] + a0.x) * inv0, (o[nt][1] + a0.y) * inv0);
            *reinterpret_cast<float2*>(&Ob[(size_t)(qrow + 8) * 64 + 8 * nt + 2 * mm]) =
                make_float2((o[nt][2] + a1.x) * inv1, (o[nt][3] + a1.y) * inv1);
        }
    }
}

// ---------------------------------------------------------------------------
// Bilinear x2 upsample (unchanged)
// ---------------------------------------------------------------------------
__global__ void upsample_kernel(const float* __restrict__ in, float* __restrict__ out) {
    int tid = threadIdx.x;
    int c = tid & 63;
    int p = blockIdx.x * 4 + (tid >> 6);
    int b = p >> 14;
    int rem = p & 16383;
    int y = rem >> 7, x = rem & 127;
    float sy = (float)y * (63.0f / 127.0f);
    int y0 = (int)sy; float wy = sy - (float)y0; int y1 = min(y0 + 1, 63);
    float sx = (float)x * (63.0f / 127.0f);
    int x0 = (int)sx; float wx = sx - (float)x0; int x1 = min(x0 + 1, 63);
    const float* base = in + (size_t)b * NTOK * 64;
    float v00 = base[((size_t)y0 * 64 + x0) * 64 + c];
    float v01 = base[((size_t)y0 * 64 + x1) * 64 + c];
    float v10 = base[((size_t)y1 * 64 + x0) * 64 + c];
    float v11 = base[((size_t)y1 * 64 + x1) * 64 + c];
    float r0 = v00 * (1.0f - wx) + v01 * wx;
    float r1 = v10 * (1.0f - wx) + v11 * wx;
    out[(((size_t)b * 64 + c) * 128 + y) * 128 + x] = r0 * (1.0f - wy) + r1 * wy;
}

// ---------------------------------------------------------------------------
extern "C" void kernel_launch(void* const* d_in, const int* in_sizes, int n_in,
                              void* d_out, int out_size) {
    const float* x       = (const float*)d_in[0];
    const float* Wq      = (const float*)d_in[1];
    const float* bq      = (const float*)d_in[2];
    const float* Wk      = (const float*)d_in[3];
    const float* bk      = (const float*)d_in[4];
    const float* Wv      = (const float*)d_in[5];
    const float* bv      = (const float*)d_in[6];
    const float* Wl      = (const float*)d_in[7];
    const float* bl      = (const float*)d_in[8];
    const float* Wo      = (const float*)d_in[9];
    const float* bo      = (const float*)d_in[10];
    const float* Wp      = (const float*)d_in[11];
    const float* bp      = (const float*)d_in[12];
    const float* sch_dw  = (const float*)d_in[13];
    const float* sch_dwb = (const float*)d_in[14];
    const float* sch_pw  = (const float*)d_in[15];
    const float* sch_pwb = (const float*)d_in[16];
    const float* scv_dw  = (const float*)d_in[17];
    const float* scv_dwb = (const float*)d_in[18];
    const float* scv_pw  = (const float*)d_in[19];
    const float* scv_pwb = (const float*)d_in[20];
    const float* convh_w = (const float*)d_in[21];
    const float* convh_b = (const float*)d_in[22];
    const float* dsc_dw  = (const float*)d_in[23];
    const float* dsc_dwb = (const float*)d_in[24];
    const float* dsc_pw  = (const float*)d_in[25];
    const float* dsc_pwb = (const float*)d_in[26];
    const float* ln_g    = (const float*)d_in[27];
    const float* ln_b    = (const float*)d_in[28];
    float* outp = (float*)d_out;

    float* S = nullptr; float* gap = nullptr;
    cudaGetSymbolAddress((void**)&S, g_scratch);
    cudaGetSymbolAddress((void**)&gap, g_gap);

    float* xp    = S + 0  * BUF_FLOATS;
    float* q     = S + 1  * BUF_FLOATS;
    float* k     = S + 2  * BUF_FLOATS;
    float* v     = S + 3  * BUF_FLOATS;
    float* xV    = S + 4  * BUF_FLOATS;
    float* attn1 = S + 5  * BUF_FLOATS;
    float* pl    = S + 6  * BUF_FLOATS;
    float* ph    = S + 7  * BUF_FLOATS;
    float* attn2 = S + 8  * BUF_FLOATS;
    float* pn    = S + 9  * BUF_FLOATS;
    float* dsco  = S + 10 * BUF_FLOATS;
    float* comb_h    = S + 11 * BUF_FLOATS;
    float* comb_v    = comb_h + 4096;
    float* bias_comb = comb_h + 8192;

    cudaFuncSetAttribute(attn_tc_kernel, cudaFuncAttributeMaxDynamicSharedMemorySize, 169984);
    cudaFuncSetAttribute(qkvo_tc_kernel, cudaFuncAttributeMaxDynamicSharedMemorySize, 136192);
    cudaFuncSetAttribute(linear_tc2_kernel, cudaFuncAttributeMaxDynamicSharedMemorySize, 51456);
    cudaFuncSetAttribute(linear_ln_kernel, cudaFuncAttributeMaxDynamicSharedMemorySize, 51968);
    cudaFuncSetAttribute(strip_tc_kernel, cudaFuncAttributeMaxDynamicSharedMemorySize, 102656);
    cudaFuncSetAttribute(dsc_tc_kernel, cudaFuncAttributeMaxDynamicSharedMemorySize, 51456);
    cudaFuncSetAttribute(comb_kernel, cudaFuncAttributeMaxDynamicSharedMemorySize, 49152);

    // pooled tokens + GAP + composed strip weights
    avgpool_kernel<<<BATCH * 64, 256>>>(x, xp);
    gap_kernel<<<BATCH * CH, 256>>>(x, gap);
    comb_kernel<<<1, 256, 49152>>>(convh_w, convh_b, sch_pw, sch_pwb, scv_pw, scv_pwb,
                                   comb_h, comb_v, bias_comb);

    // q/k/v (gated) + xV (plain)
    qkvo_tc_kernel<<<128, 512, 136192>>>(xp, gap, Wq, bq, Wk, bk, Wv, bv, Wo, bo, q, k, v, xV);

    // self-attention -> prompt_l
    attn_tc_kernel<<<dim3(32, BATCH), 512, 169984>>>(q, k, v, attn1);
    linear_tc2_kernel<<<128, 512, 51456>>>(attn1, Wl, bl, nullptr, pl);

    // high-frequency branch (fused)
    strip_tc_kernel<<<128, 512, 102656>>>(xp, sch_dw, sch_dwb, scv_dw, scv_dwb,
                                          comb_h, comb_v, bias_comb, ph);

    // cross-attention -> prompt, +xV residual, LayerNorm (fused)
    attn_tc_kernel<<<dim3(32, BATCH), 512, 169984>>>(ph, pl, xV, attn2);
    linear_ln_kernel<<<128, 256, 51968>>>(attn2, Wp, bp, xV, ln_g, ln_b, pn);

    // dsc: dw3x3+gelu staged, pw matmul + residual (fused)
    dsc_tc_kernel<<<128, 512, 51456>>>(pn, dsc_dw, dsc_dwb, dsc_pw, dsc_pwb, dsco);

    // bilinear x2 upsample
    upsample_kernel<<<BATCH * 128 * 128 / 4, 256>>>(dsco, outp);

    (void)in_sizes; (void)n_in; (void)out_size;
}

// round 16
// speedup vs baseline: 1.2199x; 1.2199x over previous
#include <cuda_runtime.h>
#include <math.h>
#include <stdint.h>

#define BATCH   4
#define CH      64
#define NTOK    4096
#define TOKALL  16384
#define QSCALE  (0.125f * 1.4426950408889634f)   // scale * log2(e)
#define BUF_FLOATS 1048576

__device__ float g_scratch[14 * BUF_FLOATS];
__device__ float g_gap[BATCH * CH];

__device__ __forceinline__ float gelu_exact(float x) {
    return 0.5f * x * (1.0f + erff(x * 0.70710678118654752440f));
}
__device__ __forceinline__ float tf32r(float x) {
    float r; asm("cvt.rna.tf32.f32 %0, %1;" : "=f"(r) : "f"(x)); return r;
}
__device__ __forceinline__ float ex2(float x) {
    float r; asm("ex2.approx.f32 %0, %1;" : "=f"(r) : "f"(x)); return r;
}
__device__ __forceinline__ void mma_tf32(float d[4], const unsigned a[4], unsigned b0, unsigned b1) {
    asm("mma.sync.aligned.m16n8k8.row.col.f32.tf32.tf32.f32 "
        "{%0,%1,%2,%3},{%4,%5,%6,%7},{%8,%9},{%0,%1,%2,%3};"
        : "+f"(d[0]), "+f"(d[1]), "+f"(d[2]), "+f"(d[3])
        : "r"(a[0]), "r"(a[1]), "r"(a[2]), "r"(a[3]), "r"(b0), "r"(b1));
}
__device__ __forceinline__ void cp16(void* smem_dst, const void* gsrc) {
    unsigned u = (unsigned)__cvta_generic_to_shared(smem_dst);
    asm volatile("cp.async.cg.shared.global [%0], [%1], 16;" :: "r"(u), "l"(gsrc));
}

// W pair-packing position for element (o, ci): {W[o][8ks+mm], W[o][8ks+mm+4]}
__device__ __forceinline__ int wpos(int o, int ci) {
    return (ci >> 3) * 512 + o * 8 + (ci & 3) * 2 + ((ci >> 2) & 1);
}
// A-fragments for rows r0, r0+8 from X[.][68] tile (tf32 pre-converted).
__device__ __forceinline__ void load_afrag(unsigned a[8][4], const float* X, int r0, int mm) {
#pragma unroll
    for (int ks = 0; ks < 8; ks++) {
        a[ks][0] = __float_as_uint(X[r0 * 68 + 8 * ks + mm]);
        a[ks][1] = __float_as_uint(X[(r0 + 8) * 68 + 8 * ks + mm]);
        a[ks][2] = __float_as_uint(X[r0 * 68 + 8 * ks + mm + 4]);
        a[ks][3] = __float_as_uint(X[(r0 + 8) * 68 + 8 * ks + mm + 4]);
    }
}
// 8-nt variants (full 64-col row per warp)
__device__ __forceinline__ void init_acc(float acc[8][4], const float* bs, int mm) {
#pragma unroll
    for (int nt = 0; nt < 8; nt++) {
        float b0 = bs[8 * nt + 2 * mm], b1 = bs[8 * nt + 2 * mm + 1];
        acc[nt][0] = b0; acc[nt][1] = b1; acc[nt][2] = b0; acc[nt][3] = b1;
    }
}
__device__ __forceinline__ void mm_core(float acc[8][4], const unsigned a[8][4],
                                        const float* WsP, int gr, int mm) {
#pragma unroll
    for (int ks = 0; ks < 8; ks++)
#pragma unroll
        for (int nt = 0; nt < 8; nt++) {
            float2 bb = *reinterpret_cast<const float2*>(&WsP[ks * 512 + (8 * nt + gr) * 8 + mm * 2]);
            mma_tf32(acc[nt], a[ks], __float_as_uint(bb.x), __float_as_uint(bb.y));
        }
}
__device__ __forceinline__ void store_acc(const float acc[8][4], float* out,
                                          int t0, int r0, int mm) {
#pragma unroll
    for (int nt = 0; nt < 8; nt++) {
        *reinterpret_cast<float2*>(&out[(size_t)(t0 + r0) * 64 + 8 * nt + 2 * mm]) =
            make_float2(acc[nt][0], acc[nt][1]);
        *reinterpret_cast<float2*>(&out[(size_t)(t0 + r0 + 8) * 64 + 8 * nt + 2 * mm]) =
            make_float2(acc[nt][2], acc[nt][3]);
    }
}
// 4-nt variants (N-split: warp owns cols [8*nt0, 8*nt0+32))
__device__ __forceinline__ void init_acc4(float acc[4][4], const float* bs, int mm, int nt0) {
#pragma unroll
    for (int nt = 0; nt < 4; nt++) {
        float b0 = bs[8 * (nt0 + nt) + 2 * mm], b1 = bs[8 * (nt0 + nt) + 2 * mm + 1];
        acc[nt][0] = b0; acc[nt][1] = b1; acc[nt][2] = b0; acc[nt][3] = b1;
    }
}
__device__ __forceinline__ void mm_core4(float acc[4][4], const unsigned a[8][4],
                                         const float* WsP, int gr, int mm, int nt0) {
#pragma unroll
    for (int ks = 0; ks < 8; ks++)
#pragma unroll
        for (int nt = 0; nt < 4; nt++) {
            float2 bb = *reinterpret_cast<const float2*>(
                &WsP[ks * 512 + (8 * (nt0 + nt) + gr) * 8 + mm * 2]);
            mma_tf32(acc[nt], a[ks], __float_as_uint(bb.x), __float_as_uint(bb.y));
        }
}
__device__ __forceinline__ void store_acc4(const float acc[4][4], float* out,
                                           int t0, int r0, int mm, int nt0) {
#pragma unroll
    for (int nt = 0; nt < 4; nt++) {
        int c0 = 8 * (nt0 + nt) + 2 * mm;
        *reinterpret_cast<float2*>(&out[(size_t)(t0 + r0) * 64 + c0]) =
            make_float2(acc[nt][0], acc[nt][1]);
        *reinterpret_cast<float2*>(&out[(size_t)(t0 + r0 + 8) * 64 + c0]) =
            make_float2(acc[nt][2], acc[nt][3]);
    }
}

// ---------------------------------------------------------------------------
// avgpool 2x2: x [B,C,128,128] -> xp tokens [B*N, C]
// ---------------------------------------------------------------------------
__global__ void avgpool_kernel(const float* __restrict__ x, float* __restrict__ xp) {
    int b  = blockIdx.x >> 6;
    int hp = blockIdx.x & 63;
    const float* xb = x + (size_t)b * CH * 128 * 128;
    float* xpb = xp + ((size_t)b * NTOK + (size_t)hp * 64) * CH;
    for (int idx = threadIdx.x; idx < 64 * CH; idx += blockDim.x) {
        int c  = idx & 63;
        int wp = idx >> 6;
        const float* p = xb + ((size_t)c * 128 + 2 * hp) * 128 + 2 * wp;
        xpb[(size_t)wp * CH + c] = 0.25f * (p[0] + p[1] + p[128] + p[129]);
    }
}

__global__ void gap_kernel(const float* __restrict__ x, float* __restrict__ gap) {
    int bc = blockIdx.x;
    const float* p = x + (size_t)bc * 16384;
    float s = 0.f;
    for (int i = threadIdx.x; i < 16384; i += 256) s += p[i];
    __shared__ float red[256];
    red[threadIdx.x] = s;
    __syncthreads();
    for (int st = 128; st > 0; st >>= 1) {
        if (threadIdx.x < st) red[threadIdx.x] += red[threadIdx.x + st];
        __syncthreads();
    }
    if (threadIdx.x == 0) gap[bc] = red[0] * (1.0f / 16384.0f);
}

// ---------------------------------------------------------------------------
// Composed strip weights
// ---------------------------------------------------------------------------
__global__ void comb_kernel(const float* __restrict__ convh_w, const float* __restrict__ convh_b,
                            const float* __restrict__ sch_pw, const float* __restrict__ sch_pwb,
                            const float* __restrict__ scv_pw, const float* __restrict__ scv_pwb,
                            float* __restrict__ comb_h, float* __restrict__ comb_v,
                            float* __restrict__ bias_comb) {
    extern __shared__ float s[];
    float* A = s; float* B1 = s + 4096; float* B2 = s + 8192;
    int tid = threadIdx.x;
    for (int idx = tid; idx < 4096; idx += 256) {
        A[idx] = convh_w[idx]; B1[idx] = sch_pw[idx]; B2[idx] = scv_pw[idx];
    }
    __syncthreads();
    for (int e = tid; e < 4096; e += 256) {
        int o = e >> 6, j = e & 63;
        float sh = 0.f, sv = 0.f;
        for (int i = 0; i < 64; i++) {
            float a = A[o * 64 + i];
            sh += a * B1[i * 64 + j];
            sv += a * B2[i * 64 + j];
        }
        comb_h[o * 64 + j] = sh;
        comb_v[o * 64 + j] = sv;
    }
    if (tid < 64) {
        float sb = 0.f;
        for (int i = 0; i < 64; i++) sb += A[tid * 64 + i] * (sch_pwb[i] + scv_pwb[i]);
        bias_comb[tid] = convh_b[tid] + sb;
    }
}

// ---------------------------------------------------------------------------
// TC qkvo, 512 threads: warps 0-7 -> q,k ; warps 8-15 -> v,xV.
// grid 128. smem 34048 floats.
// ---------------------------------------------------------------------------
__global__ void qkvo_tc_kernel(const float* __restrict__ xp, const float* __restrict__ gap,
                               const float* __restrict__ Wq, const float* __restrict__ bq,
                               const float* __restrict__ Wk, const float* __restrict__ bk,
                               const float* __restrict__ Wv, const float* __restrict__ bv,
                               const float* __restrict__ Wo, const float* __restrict__ bo,
                               float* __restrict__ q, float* __restrict__ k,
                               float* __restrict__ v, float* __restrict__ xV) {
    extern __shared__ __align__(16) float sm[];
    float* Xg  = sm;            // 8704
    float* Xs  = sm + 8704;     // 8704
    float* Wp4 = sm + 17408;    // 16384
    float* bs  = sm + 33792;    // 256
    int tid = threadIdx.x;
    int t0 = blockIdx.x * 128;
    int b = t0 >> 12;
    for (int idx = tid; idx < 8192; idx += 512) {
        int t = idx >> 6, c = idx & 63;
        float xv = xp[(size_t)(t0 + t) * 64 + c];
        Xs[t * 68 + c] = tf32r(xv);
        Xg[t * 68 + c] = tf32r(xv * __ldg(&gap[b * 64 + c]));
    }
    for (int idx = tid; idx < 4096; idx += 512) {
        int o = idx >> 6, ci = idx & 63;
        int pos = wpos(o, ci);
        Wp4[pos]         = tf32r(Wq[idx]);
        Wp4[4096 + pos]  = tf32r(Wk[idx]);
        Wp4[8192 + pos]  = tf32r(Wv[idx]);
        Wp4[12288 + pos] = tf32r(Wo[idx]);
    }
    if (tid < 64) {
        bs[tid] = bq[tid]; bs[64 + tid] = bk[tid];
        bs[128 + tid] = bv[tid]; bs[192 + tid] = bo[tid];
    }
    __syncthreads();
    int warp = tid >> 5, lane = tid & 31, gr = lane >> 2, mm = lane & 3;
    int r0 = (warp & 7) * 16 + gr;
    unsigned a[8][4];
    float acc[8][4];
    if (warp < 8) {
        load_afrag(a, Xg, r0, mm);
        init_acc(acc, bs, mm);       mm_core(acc, a, Wp4, gr, mm);        store_acc(acc, q, t0, r0, mm);
        init_acc(acc, bs + 64, mm);  mm_core(acc, a, Wp4 + 4096, gr, mm); store_acc(acc, k, t0, r0, mm);
    } else {
        load_afrag(a, Xg, r0, mm);
        init_acc(acc, bs + 128, mm); mm_core(acc, a, Wp4 + 8192, gr, mm); store_acc(acc, v, t0, r0, mm);
        load_afrag(a, Xs, r0, mm);
        init_acc(acc, bs + 192, mm); mm_core(acc, a, Wp4 + 12288, gr, mm); store_acc(acc, xV, t0, r0, mm);
    }
}

// ---------------------------------------------------------------------------
// TC 64x64 linear, 512 threads N-split (no LN). grid 128. smem 12864 fl.
// ---------------------------------------------------------------------------
__global__ void linear_tc2_kernel(const float* __restrict__ in0, const float* __restrict__ W,
                                  const float* __restrict__ bias, const float* __restrict__ res,
                                  float* __restrict__ out) {
    extern __shared__ __align__(16) float sm[];
    float* Xs  = sm;           // 8704
    float* WsP = sm + 8704;    // 4096
    float* bs  = sm + 12800;   // 64
    int tid = threadIdx.x;
    int t0 = blockIdx.x * 128;
    for (int idx = tid; idx < 8192; idx += 512) {
        int t = idx >> 6, c = idx & 63;
        Xs[t * 68 + c] = tf32r(in0[(size_t)(t0 + t) * 64 + c]);
    }
    for (int idx = tid; idx < 4096; idx += 512) {
        int o = idx >> 6, ci = idx & 63;
        WsP[wpos(o, ci)] = tf32r(W[idx]);
    }
    if (tid < 64) bs[tid] = bias[tid];
    __syncthreads();
    int warp = tid >> 5, lane = tid & 31, gr = lane >> 2, mm = lane & 3;
    int r0 = (warp & 7) * 16 + gr;
    int nt0 = (warp >> 3) * 4;
    unsigned a[8][4];
    load_afrag(a, Xs, r0, mm);
    float acc[4][4];
    init_acc4(acc, bs, mm, nt0);
    mm_core4(acc, a, WsP, gr, mm, nt0);
    if (res) {
#pragma unroll
        for (int nt = 0; nt < 4; nt++) {
            int c0 = 8 * (nt0 + nt) + 2 * mm;
            float2 r0v = *reinterpret_cast<const float2*>(&res[(size_t)(t0 + r0) * 64 + c0]);
            float2 r1v = *reinterpret_cast<const float2*>(&res[(size_t)(t0 + r0 + 8) * 64 + c0]);
            acc[nt][0] += r0v.x; acc[nt][1] += r0v.y;
            acc[nt][2] += r1v.x; acc[nt][3] += r1v.y;
        }
    }
    store_acc4(acc, out, t0, r0, mm, nt0);
}

// ---------------------------------------------------------------------------
// TC linear + residual + LayerNorm (Wp path). 256 threads, grid 128.
// ---------------------------------------------------------------------------
__global__ void linear_ln_kernel(const float* __restrict__ in0, const float* __restrict__ W,
                                 const float* __restrict__ bias, const float* __restrict__ res,
                                 const float* __restrict__ lng, const float* __restrict__ lnb,
                                 float* __restrict__ out) {
    extern __shared__ __align__(16) float sm[];
    float* Xs  = sm;           // 8704
    float* WsP = sm + 8704;    // 4096
    float* bs  = sm + 12800;   // 64
    float* lg  = sm + 12864;   // 64
    float* lb  = sm + 12928;   // 64
    int tid = threadIdx.x;
    int t0 = blockIdx.x * 128;
    for (int idx = tid; idx < 8192; idx += 256) {
        int t = idx >> 6, c = idx & 63;
        Xs[t * 68 + c] = tf32r(in0[(size_t)(t0 + t) * 64 + c]);
    }
    for (int idx = tid; idx < 4096; idx += 256) {
        int o = idx >> 6, ci = idx & 63;
        WsP[wpos(o, ci)] = tf32r(W[idx]);
    }
    if (tid < 64) { bs[tid] = bias[tid]; lg[tid] = lng[tid]; lb[tid] = lnb[tid]; }
    __syncthreads();
    int warp = tid >> 5, lane = tid & 31, gr = lane >> 2, mm = lane & 3;
    int r0 = warp * 16 + gr;
    unsigned a[8][4];
    load_afrag(a, Xs, r0, mm);
    float acc[8][4];
    init_acc(acc, bs, mm);
    mm_core(acc, a, WsP, gr, mm);
#pragma unroll
    for (int nt = 0; nt < 8; nt++) {
        float2 r0v = *reinterpret_cast<const float2*>(&res[(size_t)(t0 + r0) * 64 + 8 * nt + 2 * mm]);
        float2 r1v = *reinterpret_cast<const float2*>(&res[(size_t)(t0 + r0 + 8) * 64 + 8 * nt + 2 * mm]);
        acc[nt][0] += r0v.x; acc[nt][1] += r0v.y;
        acc[nt][2] += r1v.x; acc[nt][3] += r1v.y;
    }
    float s0 = 0.f, s1 = 0.f;
#pragma unroll
    for (int nt = 0; nt < 8; nt++) { s0 += acc[nt][0] + acc[nt][1]; s1 += acc[nt][2] + acc[nt][3]; }
    s0 += __shfl_xor_sync(0xffffffffu, s0, 1); s0 += __shfl_xor_sync(0xffffffffu, s0, 2);
    s1 += __shfl_xor_sync(0xffffffffu, s1, 1); s1 += __shfl_xor_sync(0xffffffffu, s1, 2);
    float mu0 = s0 * (1.0f / 64.0f), mu1 = s1 * (1.0f / 64.0f);
    float q0 = 0.f, q1 = 0.f;
#pragma unroll
    for (int nt = 0; nt < 8; nt++) {
        float d0 = acc[nt][0] - mu0, d1 = acc[nt][1] - mu0;
        float d2 = acc[nt][2] - mu1, d3 = acc[nt][3] - mu1;
        q0 += d0 * d0 + d1 * d1; q1 += d2 * d2 + d3 * d3;
    }
    q0 += __shfl_xor_sync(0xffffffffu, q0, 1); q0 += __shfl_xor_sync(0xffffffffu, q0, 2);
    q1 += __shfl_xor_sync(0xffffffffu, q1, 1); q1 += __shfl_xor_sync(0xffffffffu, q1, 2);
    float rstd0 = rsqrtf(q0 * (1.0f / 64.0f) + 1e-5f);
    float rstd1 = rsqrtf(q1 * (1.0f / 64.0f) + 1e-5f);
#pragma unroll
    for (int nt = 0; nt < 8; nt++) {
        int c0 = 8 * nt + 2 * mm;
        acc[nt][0] = (acc[nt][0] - mu0) * rstd0 * lg[c0] + lb[c0];
        acc[nt][1] = (acc[nt][1] - mu0) * rstd0 * lg[c0 + 1] + lb[c0 + 1];
        acc[nt][2] = (acc[nt][2] - mu1) * rstd1 * lg[c0] + lb[c0];
        acc[nt][3] = (acc[nt][3] - mu1) * rstd1 * lg[c0 + 1] + lb[c0 + 1];
    }
    store_acc(acc, out, t0, r0, mm);
}

// ---------------------------------------------------------------------------
// TC strip branch, 512 threads N-split. grid 128. smem 25664 fl.
// ---------------------------------------------------------------------------
__global__ void strip_tc_kernel(const float* __restrict__ xp,
                                const float* __restrict__ sch_dw, const float* __restrict__ sch_dwb,
                                const float* __restrict__ scv_dw, const float* __restrict__ scv_dwb,
                                const float* __restrict__ comb_h, const float* __restrict__ comb_v,
                                const float* __restrict__ bias_comb, float* __restrict__ out) {
    extern __shared__ __align__(16) float sm[];
    float* Gh   = sm;           // 8704
    float* Gv   = sm + 8704;    // 8704
    float* WsPH = sm + 17408;   // 4096
    float* WsPV = sm + 21504;   // 4096
    float* bs   = sm + 25600;   // 64
    int tid = threadIdx.x;
    int t0 = blockIdx.x * 128;
    for (int idx = tid; idx < 8192; idx += 512) {
        int tt = idx >> 6, ci = idx & 63;
        int token = t0 + tt;
        int h = (token >> 6) & 63, w = token & 63;
        size_t base = (size_t)token * 64 + ci;
        float ah = sch_dwb[ci], av = scv_dwb[ci];
#pragma unroll
        for (int d = -2; d <= 2; d++) {
            int hh = h + d;
            if (hh >= 0 && hh < 64) ah += sch_dw[ci * 5 + d + 2] * xp[base + (ptrdiff_t)d * 4096];
            int ww = w + d;
            if (ww >= 0 && ww < 64) av += scv_dw[ci * 5 + d + 2] * xp[base + (ptrdiff_t)d * 64];
        }
        Gh[tt * 68 + ci] = tf32r(gelu_exact(ah));
        Gv[tt * 68 + ci] = tf32r(gelu_exact(av));
    }
    for (int idx = tid; idx < 4096; idx += 512) {
        int o = idx >> 6, ci = idx & 63;
        int pos = wpos(o, ci);
        WsPH[pos] = tf32r(comb_h[idx]);
        WsPV[pos] = tf32r(comb_v[idx]);
    }
    if (tid < 64) bs[tid] = bias_comb[tid];
    __syncthreads();
    int warp = tid >> 5, lane = tid & 31, gr = lane >> 2, mm = lane & 3;
    int r0 = (warp & 7) * 16 + gr;
    int nt0 = (warp >> 3) * 4;
    unsigned a[8][4];
    float acc[4][4];
    init_acc4(acc, bs, mm, nt0);
    load_afrag(a, Gh, r0, mm); mm_core4(acc, a, WsPH, gr, mm, nt0);
    load_afrag(a, Gv, r0, mm); mm_core4(acc, a, WsPV, gr, mm, nt0);
    store_acc4(acc, out, t0, r0, mm, nt0);
}

// ---------------------------------------------------------------------------
// TC dsc, 512 threads N-split: gelu(dw3x3(pn)) staged, matmul, +pn residual.
// ---------------------------------------------------------------------------
__global__ void dsc_tc_kernel(const float* __restrict__ pn,
                              const float* __restrict__ dsc_dw, const float* __restrict__ dsc_dwb,
                              const float* __restrict__ dsc_pw, const float* __restrict__ dsc_pwb,
                              float* __restrict__ out) {
    extern __shared__ __align__(16) float sm[];
    float* Xs  = sm;           // 8704
    float* WsP = sm + 8704;    // 4096
    float* bs  = sm + 12800;   // 64
    int tid = threadIdx.x;
    int t0 = blockIdx.x * 128;
    for (int idx = tid; idx < 8192; idx += 512) {
        int tt = idx >> 6, ci = idx & 63;
        int token = t0 + tt;
        int b = token >> 12;
        int h = (token >> 6) & 63, w = token & 63;
        float acc = dsc_dwb[ci];
#pragma unroll
        for (int ky = 0; ky < 3; ky++) {
#pragma unroll
            for (int kx = 0; kx < 3; kx++) {
                int hh = h + ky - 1, ww = w + kx - 1;
                if (hh >= 0 && hh < 64 && ww >= 0 && ww < 64) {
                    size_t src = (((size_t)b << 12) | ((size_t)hh << 6) | (size_t)ww) * 64 + ci;
                    acc += dsc_dw[ci * 9 + ky * 3 + kx] * pn[src];
                }
            }
        }
        Xs[tt * 68 + ci] = tf32r(gelu_exact(acc));
    }
    for (int idx = tid; idx < 4096; idx += 512) {
        int o = idx >> 6, ci = idx & 63;
        WsP[wpos(o, ci)] = tf32r(dsc_pw[idx]);
    }
    if (tid < 64) bs[tid] = dsc_pwb[tid];
    __syncthreads();
    int warp = tid >> 5, lane = tid & 31, gr = lane >> 2, mm = lane & 3;
    int r0 = (warp & 7) * 16 + gr;
    int nt0 = (warp >> 3) * 4;
    unsigned a[8][4];
    load_afrag(a, Xs, r0, mm);
    float acc[4][4];
    init_acc4(acc, bs, mm, nt0);
    mm_core4(acc, a, WsP, gr, mm, nt0);
#pragma unroll
    for (int nt = 0; nt < 4; nt++) {
        int c0 = 8 * (nt0 + nt) + 2 * mm;
        float2 r0v = *reinterpret_cast<const float2*>(&pn[(size_t)(t0 + r0) * 64 + c0]);
        float2 r1v = *reinterpret_cast<const float2*>(&pn[(size_t)(t0 + r0 + 8) * 64 + c0]);
        acc[nt][0] += r0v.x; acc[nt][1] += r0v.y;
        acc[nt][2] += r1v.x; acc[nt][3] += r1v.y;
    }
    store_acc4(acc, out, t0, r0, mm, nt0);
}

// ---------------------------------------------------------------------------
// Tensor-core flash attention, cp.async double-buffered pipeline.
// 256 threads / 8 warps, Q tile 128, grid (32, B).
// K/V staged RAW fp32 via cp.async.cg (mma truncates to tf32 in HW).
// K tile row-major pitch 68 (frag banks 4*gr+mm: conflict-free).
// V tile row-major pitch 72 (frag banks 8*mm+gr: conflict-free).
// smem: Qs 8704 + K 2*4352 + V 2*4608 + Ps 8704 = 35328 fl = 141312 B.
// ---------------------------------------------------------------------------
__global__ void attn_tc_kernel(const float* __restrict__ Q, const float* __restrict__ K,
                               const float* __restrict__ V, float* __restrict__ O) {
    extern __shared__ __align__(16) float sm[];
    float* Qs  = sm;               // 8704
    float* Kst = sm + 8704;        // 2 * 4352
    float* Vst = sm + 17408;       // 2 * 4608
    float* Ps  = sm + 26624;       // 8 * 1088

    int b  = blockIdx.y;
    int qt = blockIdx.x;
    const float* Qb = Q + ((size_t)b * NTOK + (size_t)qt * 128) * 64;
    const float* Kb = K + (size_t)b * NTOK * 64;
    const float* Vb = V + (size_t)b * NTOK * 64;
    float* Ob = O + ((size_t)b * NTOK + (size_t)qt * 128) * 64;

    int tid  = threadIdx.x;
    int warp = tid >> 5, lane = tid & 31;
    int gr = lane >> 2, mm = lane & 3;
    float* Psw = Ps + warp * 1088;

    // issue first K/V tile, then stage Q while it flies
    {
        float* Kd = Kst; float* Vd = Vst;
#pragma unroll
        for (int qq = tid; qq < 1024; qq += 256) {
            int j = qq >> 4, c4 = (qq & 15) * 4;
            cp16(&Kd[j * 68 + c4], Kb + j * 64 + c4);
            cp16(&Vd[j * 72 + c4], Vb + j * 64 + c4);
        }
        asm volatile("cp.async.commit_group;");
    }
    for (int idx = tid; idx < 8192; idx += 256) {
        int i = idx >> 6, c = idx & 63;
        Qs[i * 68 + c] = tf32r(Qb[idx] * QSCALE);
    }
    __syncthreads();

    unsigned qa[8][4];
    int qrow = warp * 16 + gr;
    load_afrag(qa, Qs, qrow, mm);

    float l0 = 0.f, l1 = 0.f;
    float o[8][4];
#pragma unroll
    for (int nt = 0; nt < 8; nt++)
#pragma unroll
        for (int e = 0; e < 4; e++) o[nt][e] = 0.f;

    for (int kt = 0; kt < 64; kt++) {
        int bf = kt & 1;
        // prefetch next tile into alternate buffer
        if (kt < 63) {
            const float* Kt = Kb + (size_t)(kt + 1) * 4096;
            const float* Vt = Vb + (size_t)(kt + 1) * 4096;
            float* Kd = Kst + (bf ^ 1) * 4352;
            float* Vd = Vst + (bf ^ 1) * 4608;
#pragma unroll
            for (int qq = tid; qq < 1024; qq += 256) {
                int j = qq >> 4, c4 = (qq & 15) * 4;
                cp16(&Kd[j * 68 + c4], Kt + j * 64 + c4);
                cp16(&Vd[j * 72 + c4], Vt + j * 64 + c4);
            }
            asm volatile("cp.async.commit_group;");
            asm volatile("cp.async.wait_group 1;");
        } else {
            asm volatile("cp.async.wait_group 0;");
        }
        __syncthreads();   // current buffer visible to all warps

        const float* Kd = Kst + bf * 4352;
        const float* Vd = Vst + bf * 4608;

        // S' = Q K^T (log2 domain); K raw fp32, HW-truncated to tf32
        float s[8][4];
#pragma unroll
        for (int nt = 0; nt < 8; nt++)
#pragma unroll
            for (int e = 0; e < 4; e++) s[nt][e] = 0.f;
#pragma unroll
        for (int ks = 0; ks < 8; ks++) {
#pragma unroll
            for (int nt = 0; nt < 8; nt++) {
                unsigned b0 = __float_as_uint(Kd[(8 * nt + gr) * 68 + 8 * ks + mm]);
                unsigned b1 = __float_as_uint(Kd[(8 * nt + gr) * 68 + 8 * ks + mm + 4]);
                mma_tf32(s[nt], qa[ks], b0, b1);
            }
        }

        // exp (no max), accumulate l, store P raw (HW truncates)
        float rs0 = 0.f, rs1 = 0.f;
#pragma unroll
        for (int nt = 0; nt < 8; nt++) {
            float e0 = ex2(s[nt][0]), e1 = ex2(s[nt][1]);
            float e2 = ex2(s[nt][2]), e3 = ex2(s[nt][3]);
            rs0 += e0 + e1; rs1 += e2 + e3;
            *reinterpret_cast<float2*>(&Psw[gr * 68 + 8 * nt + 2 * mm]) = make_float2(e0, e1);
            *reinterpret_cast<float2*>(&Psw[(gr + 8) * 68 + 8 * nt + 2 * mm]) = make_float2(e2, e3);
        }
        l0 += rs0; l1 += rs1;
        __syncwarp();

        // O += P V
#pragma unroll
        for (int js = 0; js < 8; js++) {
            unsigned pa[4];
            pa[0] = __float_as_uint(Psw[gr * 68 + 8 * js + mm]);
            pa[1] = __float_as_uint(Psw[(gr + 8) * 68 + 8 * js + mm]);
            pa[2] = __float_as_uint(Psw[gr * 68 + 8 * js + mm + 4]);
            pa[3] = __float_as_uint(Psw[(gr + 8) * 68 + 8 * js + mm + 4]);
#pragma unroll
            for (int nt = 0; nt < 8; nt++) {
                unsigned b0 = __float_as_uint(Vd[(8 * js + mm) * 72 + 8 * nt + gr]);
                unsigned b1 = __float_as_uint(Vd[(8 * js + mm + 4) * 72 + 8 * nt + gr]);
                mma_tf32(o[nt], pa, b0, b1);
            }
        }
        __syncthreads();   // compute done before buffer is overwritten next iter
    }

    l0 += __shfl_xor_sync(0xffffffffu, l0, 1); l0 += __shfl_xor_sync(0xffffffffu, l0, 2);
    l1 += __shfl_xor_sync(0xffffffffu, l1, 1); l1 += __shfl_xor_sync(0xffffffffu, l1, 2);
    float inv0 = 1.0f / l0, inv1 = 1.0f / l1;
#pragma unroll
    for (int nt = 0; nt < 8; nt++) {
        *reinterpret_cast<float2*>(&Ob[(size_t)qrow * 64 + 8 * nt + 2 * mm]) =
            make_float2(o[nt][0] * inv0, o[nt][1] * inv0);
        *reinterpret_cast<float2*>(&Ob[(size_t)(qrow + 8) * 64 + 8 * nt + 2 * mm]) =
            make_float2(o[nt][2] * inv1, o[nt][3] * inv1);
    }
}

// ---------------------------------------------------------------------------
// Bilinear x2 upsample (unchanged)
// ---------------------------------------------------------------------------
__global__ void upsample_kernel(const float* __restrict__ in, float* __restrict__ out) {
    int tid = threadIdx.x;
    int c = tid & 63;
    int p = blockIdx.x * 4 + (tid >> 6);
    int b = p >> 14;
    int rem = p & 16383;
    int y = rem >> 7, x = rem & 127;
    float sy = (float)y * (63.0f / 127.0f);
    int y0 = (int)sy; float wy = sy - (float)y0; int y1 = min(y0 + 1, 63);
    float sx = (float)x * (63.0f / 127.0f);
    int x0 = (int)sx; float wx = sx - (float)x0; int x1 = min(x0 + 1, 63);
    const float* base = in + (size_t)b * NTOK * 64;
    float v00 = base[((size_t)y0 * 64 + x0) * 64 + c];
    float v01 = base[((size_t)y0 * 64 + x1) * 64 + c];
    float v10 = base[((size_t)y1 * 64 + x0) * 64 + c];
    float v11 = base[((size_t)y1 * 64 + x1) * 64 + c];
    float r0 = v00 * (1.0f - wx) + v01 * wx;
    float r1 = v10 * (1.0f - wx) + v11 * wx;
    out[(((size_t)b * 64 + c) * 128 + y) * 128 + x] = r0 * (1.0f - wy) + r1 * wy;
}

// ---------------------------------------------------------------------------
extern "C" void kernel_launch(void* const* d_in, const int* in_sizes, int n_in,
                              void* d_out, int out_size) {
    const float* x       = (const float*)d_in[0];
    const float* Wq      = (const float*)d_in[1];
    const float* bq      = (const float*)d_in[2];
    const float* Wk      = (const float*)d_in[3];
    const float* bk      = (const float*)d_in[4];
    const float* Wv      = (const float*)d_in[5];
    const float* bv      = (const float*)d_in[6];
    const float* Wl      = (const float*)d_in[7];
    const float* bl      = (const float*)d_in[8];
    const float* Wo      = (const float*)d_in[9];
    const float* bo      = (const float*)d_in[10];
    const float* Wp      = (const float*)d_in[11];
    const float* bp      = (const float*)d_in[12];
    const float* sch_dw  = (const float*)d_in[13];
    const float* sch_dwb = (const float*)d_in[14];
    const float* sch_pw  = (const float*)d_in[15];
    const float* sch_pwb = (const float*)d_in[16];
    const float* scv_dw  = (const float*)d_in[17];
    const float* scv_dwb = (const float*)d_in[18];
    const float* scv_pw  = (const float*)d_in[19];
    const float* scv_pwb = (const float*)d_in[20];
    const float* convh_w = (const float*)d_in[21];
    const float* convh_b = (const float*)d_in[22];
    const float* dsc_dw  = (const float*)d_in[23];
    const float* dsc_dwb = (const float*)d_in[24];
    const float* dsc_pw  = (const float*)d_in[25];
    const float* dsc_pwb = (const float*)d_in[26];
    const float* ln_g    = (const float*)d_in[27];
    const float* ln_b    = (const float*)d_in[28];
    float* outp = (float*)d_out;

    float* S = nullptr; float* gap = nullptr;
    cudaGetSymbolAddress((void**)&S, g_scratch);
    cudaGetSymbolAddress((void**)&gap, g_gap);

    float* xp    = S + 0  * BUF_FLOATS;
    float* q     = S + 1  * BUF_FLOATS;
    float* k     = S + 2  * BUF_FLOATS;
    float* v     = S + 3  * BUF_FLOATS;
    float* xV    = S + 4  * BUF_FLOATS;
    float* attn1 = S + 5  * BUF_FLOATS;
    float* pl    = S + 6  * BUF_FLOATS;
    float* ph    = S + 7  * BUF_FLOATS;
    float* attn2 = S + 8  * BUF_FLOATS;
    float* pn    = S + 9  * BUF_FLOATS;
    float* dsco  = S + 10 * BUF_FLOATS;
    float* comb_h    = S + 11 * BUF_FLOATS;
    float* comb_v    = comb_h + 4096;
    float* bias_comb = comb_h + 8192;

    cudaFuncSetAttribute(attn_tc_kernel, cudaFuncAttributeMaxDynamicSharedMemorySize, 141312);
    cudaFuncSetAttribute(qkvo_tc_kernel, cudaFuncAttributeMaxDynamicSharedMemorySize, 136192);
    cudaFuncSetAttribute(linear_tc2_kernel, cudaFuncAttributeMaxDynamicSharedMemorySize, 51456);
    cudaFuncSetAttribute(linear_ln_kernel, cudaFuncAttributeMaxDynamicSharedMemorySize, 51968);
    cudaFuncSetAttribute(strip_tc_kernel, cudaFuncAttributeMaxDynamicSharedMemorySize, 102656);
    cudaFuncSetAttribute(dsc_tc_kernel, cudaFuncAttributeMaxDynamicSharedMemorySize, 51456);
    cudaFuncSetAttribute(comb_kernel, cudaFuncAttributeMaxDynamicSharedMemorySize, 49152);

    // pooled tokens + GAP + composed strip weights
    avgpool_kernel<<<BATCH * 64, 256>>>(x, xp);
    gap_kernel<<<BATCH * CH, 256>>>(x, gap);
    comb_kernel<<<1, 256, 49152>>>(convh_w, convh_b, sch_pw, sch_pwb, scv_pw, scv_pwb,
                                   comb_h, comb_v, bias_comb);

    // q/k/v (gated) + xV (plain)
    qkvo_tc_kernel<<<128, 512, 136192>>>(xp, gap, Wq, bq, Wk, bk, Wv, bv, Wo, bo, q, k, v, xV);

    // self-attention -> prompt_l
    attn_tc_kernel<<<dim3(32, BATCH), 256, 141312>>>(q, k, v, attn1);
    linear_tc2_kernel<<<128, 512, 51456>>>(attn1, Wl, bl, nullptr, pl);

    // high-frequency branch (fused)
    strip_tc_kernel<<<128, 512, 102656>>>(xp, sch_dw, sch_dwb, scv_dw, scv_dwb,
                                          comb_h, comb_v, bias_comb, ph);

    // cross-attention -> prompt, +xV residual, LayerNorm (fused)
    attn_tc_kernel<<<dim3(32, BATCH), 256, 141312>>>(ph, pl, xV, attn2);
    linear_ln_kernel<<<128, 256, 51968>>>(attn2, Wp, bp, xV, ln_g, ln_b, pn);

    // dsc: dw3x3+gelu staged, pw matmul + residual (fused)
    dsc_tc_kernel<<<128, 512, 51456>>>(pn, dsc_dw, dsc_dwb, dsc_pw, dsc_pwb, dsco);

    // bilinear x2 upsample
    upsample_kernel<<<BATCH * 128 * 128 / 4, 256>>>(dsco, outp);

    (void)in_sizes; (void)n_in; (void)out_size;
}